// round 14
// baseline (speedup 1.0000x reference)
#include <cuda_runtime.h>
#include <math.h>

#define Bn 1024
#define Sn 512
#define Vn 50000
#define En 300
#define Hn 800
#define Tn 50
#define NBLK 782           // ceil(50000/64) mma blocks
#define NEXP 196           // exp-pass blocks
#define KCH 152
#define LDK 156
#define KHP 912            // head K padded (6 * 152)

// ---------------- scratch (device globals; no allocation) ----------------
__device__ __align__(16) float g_x[Bn * En];
__device__ __align__(16) float g_h[Bn * Hn];
__device__ __align__(16) float g_W1T[Hn * 304];          // W1 transposed, K padded to 304
__device__ __align__(16) float g_WheadT[128 * KHP];      // [Wmu|Wlv]^T, K padded to 912
__device__ float g_mu[Bn * Tn];
__device__ float g_lv[Bn * Tn];
__device__ __align__(16) float g_betaT[(size_t)Vn * 64]; // logitsT -> e (unnormalized beta)
__device__ float g_bmax[NBLK * 64];
__device__ float g_bsum[NEXP * 64];
__device__ float g_rmax[64];
__device__ float g_rinv[64];
__device__ float g_thetaS[Bn * 64];
__device__ float g_recon[Bn];
__device__ float g_kl[Bn];

// ---------------- kernel 1: x[b,:] = (1/cnt) * sum_valid rho[id,:] ----------------
// 4 token-groups x 75 threads; ILP-8: 8 independent LDG.128 in flight per thread.
__global__ void k_gather(const int* __restrict__ ids, const float* __restrict__ rho)
{
    __shared__ __align__(16) int sid[Sn];
    __shared__ __align__(16) float sx[4][304];
    __shared__ float s_inv;
    int b = blockIdx.x, tid = threadIdx.x;  // 320 threads
    for (int i = tid; i < Sn; i += 320) {
        int v = ids[b * Sn + i];
        sid[i] = (v == 1 || v == 2) ? -1 : v;
    }
    __syncthreads();
    if (tid < 32) {
        int c = 0;
        for (int i = tid; i < Sn; i += 32) c += (sid[i] >= 0);
#pragma unroll
        for (int o = 16; o; o >>= 1) c += __shfl_down_sync(0xffffffffu, c, o);
        if (tid == 0) s_inv = 1.0f / (float)c;
    }
    __syncthreads();
    if (tid < 300) {
        int g = tid / 75;
        int d = tid % 75;
        const float4* R = reinterpret_cast<const float4*>(rho);
        float4 a0 = {0,0,0,0}, a1 = {0,0,0,0}, a2 = {0,0,0,0}, a3 = {0,0,0,0};
        float4 a4 = {0,0,0,0}, a5 = {0,0,0,0}, a6 = {0,0,0,0}, a7 = {0,0,0,0};
        const int* sg = sid + g;
#pragma unroll 1
        for (int i = 0; i < 128; i += 8) {
            int v0 = sg[4 * (i + 0)];
            int v1 = sg[4 * (i + 1)];
            int v2 = sg[4 * (i + 2)];
            int v3 = sg[4 * (i + 3)];
            int v4 = sg[4 * (i + 4)];
            int v5 = sg[4 * (i + 5)];
            int v6 = sg[4 * (i + 6)];
            int v7 = sg[4 * (i + 7)];
            if (v0 >= 0) { float4 f = __ldg(&R[(size_t)v0 * 75 + d]); a0.x += f.x; a0.y += f.y; a0.z += f.z; a0.w += f.w; }
            if (v1 >= 0) { float4 f = __ldg(&R[(size_t)v1 * 75 + d]); a1.x += f.x; a1.y += f.y; a1.z += f.z; a1.w += f.w; }
            if (v2 >= 0) { float4 f = __ldg(&R[(size_t)v2 * 75 + d]); a2.x += f.x; a2.y += f.y; a2.z += f.z; a2.w += f.w; }
            if (v3 >= 0) { float4 f = __ldg(&R[(size_t)v3 * 75 + d]); a3.x += f.x; a3.y += f.y; a3.z += f.z; a3.w += f.w; }
            if (v4 >= 0) { float4 f = __ldg(&R[(size_t)v4 * 75 + d]); a4.x += f.x; a4.y += f.y; a4.z += f.z; a4.w += f.w; }
            if (v5 >= 0) { float4 f = __ldg(&R[(size_t)v5 * 75 + d]); a5.x += f.x; a5.y += f.y; a5.z += f.z; a5.w += f.w; }
            if (v6 >= 0) { float4 f = __ldg(&R[(size_t)v6 * 75 + d]); a6.x += f.x; a6.y += f.y; a6.z += f.z; a6.w += f.w; }
            if (v7 >= 0) { float4 f = __ldg(&R[(size_t)v7 * 75 + d]); a7.x += f.x; a7.y += f.y; a7.z += f.z; a7.w += f.w; }
        }
        float4 acc;
        acc.x = ((a0.x + a1.x) + (a2.x + a3.x)) + ((a4.x + a5.x) + (a6.x + a7.x));
        acc.y = ((a0.y + a1.y) + (a2.y + a3.y)) + ((a4.y + a5.y) + (a6.y + a7.y));
        acc.z = ((a0.z + a1.z) + (a2.z + a3.z)) + ((a4.z + a5.z) + (a6.z + a7.z));
        acc.w = ((a0.w + a1.w) + (a2.w + a3.w)) + ((a4.w + a5.w) + (a6.w + a7.w));
        *reinterpret_cast<float4*>(&sx[g][4 * d]) = acc;
    }
    __syncthreads();
    if (tid < 300) {
        float r = (sx[0][tid] + sx[1][tid]) + (sx[2][tid] + sx[3][tid]);
        g_x[b * En + tid] = r * s_inv;
    }
}

// ---------------- W1 [300][800] -> W1T [800][304] (zero-padded K) ----------------
__global__ void k_transW1(const float* __restrict__ W1)
{
    __shared__ float tile[32][33];
    int kb = blockIdx.y * 32, nb = blockIdx.x * 32;
    int tx = threadIdx.x & 31, ty = threadIdx.x >> 5;
#pragma unroll
    for (int i = 0; i < 32; i += 8) {
        int k = kb + ty + i, n = nb + tx;
        tile[ty + i][tx] = (k < En && n < Hn) ? W1[k * Hn + n] : 0.f;
    }
    __syncthreads();
#pragma unroll
    for (int i = 0; i < 32; i += 8) {
        int n = nb + ty + i, k = kb + tx;
        if (n < Hn && k < 304) g_W1T[n * 304 + k] = tile[tx][ty + i];
    }
}

// ---------------- [Wmu|Wlv] -> WheadT [128][912] ----------------
__global__ void k_transWhead(const float* __restrict__ Wmu, const float* __restrict__ Wlv)
{
    int idx = blockIdx.x * 256 + threadIdx.x;
    if (idx < 128 * KHP) {
        int c = idx / KHP, k = idx % KHP;
        float v = 0.f;
        if (k < Hn) {
            if (c < 50)       v = Wmu[k * Tn + c];
            else if (c < 100) v = Wlv[k * Tn + (c - 50)];
        }
        g_WheadT[idx] = v;
    }
}

// ---------------- h = relu(x @ W1 + b1) via tf32 mma ----------------
__global__ void k_hgemm_mma(const float* __restrict__ b1)
{
    extern __shared__ float sm[];
    float* As = sm;
    float* Bs = sm + 64 * LDK;
    int tid = threadIdx.x;
    int lane = tid & 31, warp = tid >> 5;
    int gid = lane >> 2, tig = lane & 3;
    int wm = warp >> 1, wn = warp & 1;
    int m0 = blockIdx.y * 64, n0 = blockIdx.x * 64;
    float c[4][4] = {};

    for (int ch = 0; ch < 2; ch++) {
        int kbase = ch * KCH;
        __syncthreads();
        for (int i = tid; i < 64 * 39; i += 256) {
            int row = i / 39, q = i % 39;
            int col = q * 4;
            int gk = kbase + col;
            float4 v = make_float4(0.f, 0.f, 0.f, 0.f);
            if (q < 38 && gk < En)
                v = *reinterpret_cast<const float4*>(&g_x[(size_t)(m0 + row) * En + gk]);
            unsigned t0, t1, t2, t3;
            asm("cvt.rna.tf32.f32 %0, %1;" : "=r"(t0) : "f"(v.x));
            asm("cvt.rna.tf32.f32 %0, %1;" : "=r"(t1) : "f"(v.y));
            asm("cvt.rna.tf32.f32 %0, %1;" : "=r"(t2) : "f"(v.z));
            asm("cvt.rna.tf32.f32 %0, %1;" : "=r"(t3) : "f"(v.w));
            *reinterpret_cast<float4*>(&As[row * LDK + col]) =
                make_float4(__uint_as_float(t0), __uint_as_float(t1),
                            __uint_as_float(t2), __uint_as_float(t3));
        }
        for (int i = tid; i < 64 * 39; i += 256) {
            int row = i / 39, q = i % 39;
            int col = q * 4;
            int gk = kbase + col;
            int n = n0 + row;
            float4 x = make_float4(0.f, 0.f, 0.f, 0.f);
            if (q < 38 && n < Hn)
                x = *reinterpret_cast<const float4*>(&g_W1T[(size_t)n * 304 + gk]);
            unsigned t0, t1, t2, t3;
            asm("cvt.rna.tf32.f32 %0, %1;" : "=r"(t0) : "f"(x.x));
            asm("cvt.rna.tf32.f32 %0, %1;" : "=r"(t1) : "f"(x.y));
            asm("cvt.rna.tf32.f32 %0, %1;" : "=r"(t2) : "f"(x.z));
            asm("cvt.rna.tf32.f32 %0, %1;" : "=r"(t3) : "f"(x.w));
            *reinterpret_cast<float4*>(&Bs[row * LDK + col]) =
                make_float4(__uint_as_float(t0), __uint_as_float(t1),
                            __uint_as_float(t2), __uint_as_float(t3));
        }
        __syncthreads();

        const float* Ap = As + (wm * 16 + gid) * LDK + tig;
#pragma unroll
        for (int ks = 0; ks < 19; ks++) {
            int k = ks * 8;
            unsigned a0 = __float_as_uint(Ap[k]);
            unsigned a1 = __float_as_uint(Ap[8 * LDK + k]);
            unsigned a2 = __float_as_uint(Ap[k + 4]);
            unsigned a3 = __float_as_uint(Ap[8 * LDK + k + 4]);
#pragma unroll
            for (int nt = 0; nt < 4; nt++) {
                const float* Bp = Bs + (wn * 32 + nt * 8 + gid) * LDK + tig + k;
                unsigned b0 = __float_as_uint(Bp[0]);
                unsigned b1v = __float_as_uint(Bp[4]);
                asm volatile(
                    "mma.sync.aligned.m16n8k8.row.col.f32.tf32.tf32.f32 "
                    "{%0,%1,%2,%3}, {%4,%5,%6,%7}, {%8,%9}, {%0,%1,%2,%3};"
                    : "+f"(c[nt][0]), "+f"(c[nt][1]), "+f"(c[nt][2]), "+f"(c[nt][3])
                    : "r"(a0), "r"(a1), "r"(a2), "r"(a3), "r"(b0), "r"(b1v));
            }
        }
    }

    int r0 = m0 + wm * 16 + gid;
    int colbase = n0 + wn * 32 + tig * 2;
#pragma unroll
    for (int nt = 0; nt < 4; nt++) {
        int col = colbase + nt * 8;
        if (col < Hn) {
            float bv0 = __ldg(&b1[col]), bv1 = __ldg(&b1[col + 1]);
            float2 o0 = make_float2(fmaxf(c[nt][0] + bv0, 0.f), fmaxf(c[nt][1] + bv1, 0.f));
            float2 o1 = make_float2(fmaxf(c[nt][2] + bv0, 0.f), fmaxf(c[nt][3] + bv1, 0.f));
            *reinterpret_cast<float2*>(&g_h[(size_t)r0 * Hn + col]) = o0;
            *reinterpret_cast<float2*>(&g_h[(size_t)(r0 + 8) * Hn + col]) = o1;
        }
    }
}

// ---------------- mu/lv = h @ [Wmu|Wlv] + bias via tf32 mma ----------------
__global__ void k_head_mma(const float* __restrict__ bmu, const float* __restrict__ blv)
{
    extern __shared__ float sm[];
    float* As = sm;
    float* Bs = sm + 64 * LDK;
    int tid = threadIdx.x;
    int lane = tid & 31, warp = tid >> 5;
    int gid = lane >> 2, tig = lane & 3;
    int wm = warp >> 1, wn = warp & 1;
    int m0 = blockIdx.y * 64, n0 = blockIdx.x * 64;
    float c[4][4] = {};

    for (int ch = 0; ch < 6; ch++) {
        int kbase = ch * KCH;
        __syncthreads();
        for (int i = tid; i < 64 * 39; i += 256) {
            int row = i / 39, q = i % 39;
            int col = q * 4;
            int gk = kbase + col;
            float4 v = make_float4(0.f, 0.f, 0.f, 0.f);
            if (q < 38 && gk < Hn)
                v = *reinterpret_cast<const float4*>(&g_h[(size_t)(m0 + row) * Hn + gk]);
            unsigned t0, t1, t2, t3;
            asm("cvt.rna.tf32.f32 %0, %1;" : "=r"(t0) : "f"(v.x));
            asm("cvt.rna.tf32.f32 %0, %1;" : "=r"(t1) : "f"(v.y));
            asm("cvt.rna.tf32.f32 %0, %1;" : "=r"(t2) : "f"(v.z));
            asm("cvt.rna.tf32.f32 %0, %1;" : "=r"(t3) : "f"(v.w));
            *reinterpret_cast<float4*>(&As[row * LDK + col]) =
                make_float4(__uint_as_float(t0), __uint_as_float(t1),
                            __uint_as_float(t2), __uint_as_float(t3));
        }
        for (int i = tid; i < 64 * 39; i += 256) {
            int row = i / 39, q = i % 39;
            int col = q * 4;
            int gk = kbase + col;
            float4 x = make_float4(0.f, 0.f, 0.f, 0.f);
            if (q < 38)
                x = *reinterpret_cast<const float4*>(&g_WheadT[(size_t)(n0 + row) * KHP + gk]);
            unsigned t0, t1, t2, t3;
            asm("cvt.rna.tf32.f32 %0, %1;" : "=r"(t0) : "f"(x.x));
            asm("cvt.rna.tf32.f32 %0, %1;" : "=r"(t1) : "f"(x.y));
            asm("cvt.rna.tf32.f32 %0, %1;" : "=r"(t2) : "f"(x.z));
            asm("cvt.rna.tf32.f32 %0, %1;" : "=r"(t3) : "f"(x.w));
            *reinterpret_cast<float4*>(&Bs[row * LDK + col]) =
                make_float4(__uint_as_float(t0), __uint_as_float(t1),
                            __uint_as_float(t2), __uint_as_float(t3));
        }
        __syncthreads();

        const float* Ap = As + (wm * 16 + gid) * LDK + tig;
#pragma unroll
        for (int ks = 0; ks < 19; ks++) {
            int k = ks * 8;
            unsigned a0 = __float_as_uint(Ap[k]);
            unsigned a1 = __float_as_uint(Ap[8 * LDK + k]);
            unsigned a2 = __float_as_uint(Ap[k + 4]);
            unsigned a3 = __float_as_uint(Ap[8 * LDK + k + 4]);
#pragma unroll
            for (int nt = 0; nt < 4; nt++) {
                const float* Bp = Bs + (wn * 32 + nt * 8 + gid) * LDK + tig + k;
                unsigned b0 = __float_as_uint(Bp[0]);
                unsigned b1v = __float_as_uint(Bp[4]);
                asm volatile(
                    "mma.sync.aligned.m16n8k8.row.col.f32.tf32.tf32.f32 "
                    "{%0,%1,%2,%3}, {%4,%5,%6,%7}, {%8,%9}, {%0,%1,%2,%3};"
                    : "+f"(c[nt][0]), "+f"(c[nt][1]), "+f"(c[nt][2]), "+f"(c[nt][3])
                    : "r"(a0), "r"(a1), "r"(a2), "r"(a3), "r"(b0), "r"(b1v));
            }
        }
    }

    int r0 = m0 + wm * 16 + gid;
    int colbase = n0 + wn * 32 + tig * 2;
#pragma unroll
    for (int nt = 0; nt < 4; nt++) {
#pragma unroll
        for (int j = 0; j < 2; j++) {
            int col = colbase + nt * 8 + j;
            float v0 = c[nt][j], v1 = c[nt][2 + j];
            if (col < 50) {
                float bb = __ldg(&bmu[col]);
                g_mu[(size_t)r0 * Tn + col] = v0 + bb;
                g_mu[(size_t)(r0 + 8) * Tn + col] = v1 + bb;
            } else if (col < 100) {
                float bb = __ldg(&blv[col - 50]);
                g_lv[(size_t)r0 * Tn + (col - 50)] = v0 + bb;
                g_lv[(size_t)(r0 + 8) * Tn + (col - 50)] = v1 + bb;
            }
        }
    }
}

// ---------------- logitsT[v][64] via tf32 mma + fused transpose + max partials -------
__global__ void k_logits_mma(const float* __restrict__ alpha, const float* __restrict__ rho)
{
    extern __shared__ float sm[];
    float* As = sm;
    float* Bs = sm + 64 * LDK;
    __shared__ float pmax[2][64];
    int tid = threadIdx.x;
    int lane = tid & 31, warp = tid >> 5;
    int gid = lane >> 2, tig = lane & 3;
    int wm = warp >> 1, wn = warp & 1;
    int v0 = blockIdx.x * 64;
    float c[4][4] = {};

    for (int ch = 0; ch < 2; ch++) {
        int kbase = ch * KCH;
        __syncthreads();
        for (int i = tid; i < 64 * 39; i += 256) {
            int row = i / 39, q = i % 39;
            int col = q * 4;
            int gk = kbase + col;
            float4 v = make_float4(0.f, 0.f, 0.f, 0.f);
            if (q < 38 && row < Tn && gk < En)
                v = *reinterpret_cast<const float4*>(&alpha[(size_t)row * En + gk]);
            unsigned t0, t1, t2, t3;
            asm("cvt.rna.tf32.f32 %0, %1;" : "=r"(t0) : "f"(v.x));
            asm("cvt.rna.tf32.f32 %0, %1;" : "=r"(t1) : "f"(v.y));
            asm("cvt.rna.tf32.f32 %0, %1;" : "=r"(t2) : "f"(v.z));
            asm("cvt.rna.tf32.f32 %0, %1;" : "=r"(t3) : "f"(v.w));
            *reinterpret_cast<float4*>(&As[row * LDK + col]) =
                make_float4(__uint_as_float(t0), __uint_as_float(t1),
                            __uint_as_float(t2), __uint_as_float(t3));
        }
        for (int i = tid; i < 64 * 39; i += 256) {
            int row = i / 39, q = i % 39;
            int col = q * 4;
            int gk = kbase + col;
            int v = v0 + row;
            float4 x = make_float4(0.f, 0.f, 0.f, 0.f);
            if (q < 38 && v < Vn && gk < En)
                x = *reinterpret_cast<const float4*>(&rho[(size_t)v * En + gk]);
            unsigned t0, t1, t2, t3;
            asm("cvt.rna.tf32.f32 %0, %1;" : "=r"(t0) : "f"(x.x));
            asm("cvt.rna.tf32.f32 %0, %1;" : "=r"(t1) : "f"(x.y));
            asm("cvt.rna.tf32.f32 %0, %1;" : "=r"(t2) : "f"(x.z));
            asm("cvt.rna.tf32.f32 %0, %1;" : "=r"(t3) : "f"(x.w));
            *reinterpret_cast<float4*>(&Bs[row * LDK + col]) =
                make_float4(__uint_as_float(t0), __uint_as_float(t1),
                            __uint_as_float(t2), __uint_as_float(t3));
        }
        __syncthreads();

        const float* Ap = As + (wm * 16 + gid) * LDK + tig;
#pragma unroll
        for (int ks = 0; ks < 19; ks++) {
            int k = ks * 8;
            unsigned a0 = __float_as_uint(Ap[k]);
            unsigned a1 = __float_as_uint(Ap[8 * LDK + k]);
            unsigned a2 = __float_as_uint(Ap[k + 4]);
            unsigned a3 = __float_as_uint(Ap[8 * LDK + k + 4]);
#pragma unroll
            for (int nt = 0; nt < 4; nt++) {
                const float* Bp = Bs + (wn * 32 + nt * 8 + gid) * LDK + tig + k;
                unsigned b0 = __float_as_uint(Bp[0]);
                unsigned b1 = __float_as_uint(Bp[4]);
                asm volatile(
                    "mma.sync.aligned.m16n8k8.row.col.f32.tf32.tf32.f32 "
                    "{%0,%1,%2,%3}, {%4,%5,%6,%7}, {%8,%9}, {%0,%1,%2,%3};"
                    : "+f"(c[nt][0]), "+f"(c[nt][1]), "+f"(c[nt][2]), "+f"(c[nt][3])
                    : "r"(a0), "r"(a1), "r"(a2), "r"(a3), "r"(b0), "r"(b1));
            }
        }
    }

    int colbase = v0 + wn * 32 + tig * 2;
    float m0 = -1e30f, m1 = -1e30f;
#pragma unroll
    for (int nt = 0; nt < 4; nt++) {
        int cA = colbase + nt * 8;
        if (cA < Vn)     { m0 = fmaxf(m0, c[nt][0]); m1 = fmaxf(m1, c[nt][2]); }
        if (cA + 1 < Vn) { m0 = fmaxf(m0, c[nt][1]); m1 = fmaxf(m1, c[nt][3]); }
    }
    m0 = fmaxf(m0, __shfl_xor_sync(0xffffffffu, m0, 1));
    m0 = fmaxf(m0, __shfl_xor_sync(0xffffffffu, m0, 2));
    m1 = fmaxf(m1, __shfl_xor_sync(0xffffffffu, m1, 1));
    m1 = fmaxf(m1, __shfl_xor_sync(0xffffffffu, m1, 2));
    if (tig == 0) {
        pmax[wn][wm * 16 + gid]     = m0;
        pmax[wn][wm * 16 + gid + 8] = m1;
    }
    __syncthreads();
    if (tid < 64)
        g_bmax[blockIdx.x * 64 + tid] = fmaxf(pmax[0][tid], pmax[1][tid]);

    float* sT = sm;  // [64][65]
#pragma unroll
    for (int nt = 0; nt < 4; nt++) {
        int vl = wn * 32 + nt * 8 + tig * 2;
        int r = wm * 16 + gid;
        sT[vl * 65 + r]           = c[nt][0];
        sT[(vl + 1) * 65 + r]     = c[nt][1];
        sT[vl * 65 + r + 8]       = c[nt][2];
        sT[(vl + 1) * 65 + r + 8] = c[nt][3];
    }
    __syncthreads();
#pragma unroll
    for (int rep = 0; rep < 16; rep++) {
        int idx = rep * 256 + tid;
        int vl = idx >> 6, t = idx & 63;
        int v = v0 + vl;
        if (v < Vn) g_betaT[(size_t)v * 64 + t] = sT[vl * 65 + t];
    }
}

// ---------------- combine max partials (grid 64) ----------------
__global__ void k_maxcomb()
{
    __shared__ float red[256];
    int t = blockIdx.x, tid = threadIdx.x;
    float m = -1e30f;
#pragma unroll 4
    for (int i = tid; i < NBLK; i += 256) m = fmaxf(m, g_bmax[i * 64 + t]);
    red[tid] = m; __syncthreads();
    for (int o = 128; o; o >>= 1) {
        if (tid < o) red[tid] = fmaxf(red[tid], red[tid + o]);
        __syncthreads();
    }
    if (tid == 0) g_rmax[t] = red[0];
}

// ---------------- exp in place + sum partials ----------------
__global__ void k_beta_exp()
{
    __shared__ float srmax[64];
    __shared__ float ssum[16][64];
    int tid = threadIdx.x;
    if (tid < 64) srmax[tid] = g_rmax[tid];
    __syncthreads();
    float4* P = reinterpret_cast<float4*>(g_betaT);
    size_t base = (size_t)blockIdx.x * 4096;
    int t0 = (tid & 15) * 4;
    float rm0 = srmax[t0], rm1 = srmax[t0 + 1], rm2 = srmax[t0 + 2], rm3 = srmax[t0 + 3];
    float s0 = 0.f, s1 = 0.f, s2 = 0.f, s3 = 0.f;
#pragma unroll
    for (int k = 0; k < 16; k++) {
        size_t idx = base + (size_t)k * 256 + tid;
        if (idx < (size_t)Vn * 16) {
            float4 x = P[idx];
            x.x = expf(x.x - rm0);
            x.y = expf(x.y - rm1);
            x.z = expf(x.z - rm2);
            x.w = expf(x.w - rm3);
            s0 += x.x; s1 += x.y; s2 += x.z; s3 += x.w;
            P[idx] = x;
        }
    }
    int g = tid >> 4;
    ssum[g][t0 + 0] = s0; ssum[g][t0 + 1] = s1;
    ssum[g][t0 + 2] = s2; ssum[g][t0 + 3] = s3;
    __syncthreads();
    if (tid < 64) {
        float s = 0.f;
#pragma unroll
        for (int i = 0; i < 16; i++) s += ssum[i][tid];
        g_bsum[blockIdx.x * 64 + tid] = s;
    }
}

// ---------------- combine sum partials -> rinv (grid 64) ----------------
__global__ void k_sumcomb()
{
    __shared__ float red[256];
    int t = blockIdx.x, tid = threadIdx.x;
    float s = 0.f;
    if (tid < NEXP) s = g_bsum[tid * 64 + t];
    red[tid] = s; __syncthreads();
    for (int o = 128; o; o >>= 1) {
        if (tid < o) red[tid] += red[tid + o];
        __syncthreads();
    }
    if (tid == 0) g_rinv[t] = 1.0f / red[0];
}

// ---------------- kl + theta softmax (+ scaled theta for recon) ----------------
__global__ void k_theta_kl(float* __restrict__ out)
{
    int b = blockIdx.x, t = threadIdx.x;
    __shared__ float red[64];
    bool ok = (t < Tn);
    float mu = 0.f, lv = 0.f;
    if (ok) { mu = g_mu[b * Tn + t]; lv = g_lv[b * Tn + t]; }
    float kle = ok ? (1.f + lv - mu * mu - expf(lv)) : 0.f;
    red[t] = kle; __syncthreads();
    for (int o = 32; o; o >>= 1) { if (t < o) red[t] += red[t + o]; __syncthreads(); }
    if (t == 0) g_kl[b] = -0.5f * red[0];
    __syncthreads();
    red[t] = ok ? mu : -1e30f; __syncthreads();
    for (int o = 32; o; o >>= 1) { if (t < o) red[t] = fmaxf(red[t], red[t + o]); __syncthreads(); }
    float mx = red[0]; __syncthreads();
    float e = ok ? expf(mu - mx) : 0.f;
    red[t] = e; __syncthreads();
    for (int o = 32; o; o >>= 1) { if (t < o) red[t] += red[t + o]; __syncthreads(); }
    float inv = 1.0f / red[0];
    float th = e * inv;
    if (ok) out[b * Tn + t] = th;
    g_thetaS[b * 64 + t] = ok ? th * g_rinv[t] : 0.f;
}

// ---------------- recon: 13 float4 per token (th[52..63]=0, exact) ----------------
__global__ void k_recon(const int* __restrict__ ids)
{
    __shared__ float th[64];
    __shared__ float red[256];
    int b = blockIdx.x, tid = threadIdx.x;
    if (tid < 64) th[tid] = g_thetaS[b * 64 + tid];
    __syncthreads();
    float acc = 0.f;
#pragma unroll 1
    for (int s = tid; s < Sn; s += 256) {
        int v = ids[b * Sn + s];
        if (v == 1 || v == 2) continue;
        const float4* p = reinterpret_cast<const float4*>(g_betaT + (size_t)v * 64);
        float d = 0.f;
#pragma unroll
        for (int i = 0; i < 13; i++) {
            float4 bv = p[i];
            float4 tv = *reinterpret_cast<const float4*>(&th[i * 4]);
            d += bv.x*tv.x + bv.y*tv.y + bv.z*tv.z + bv.w*tv.w;
        }
        acc += logf(d + 1e-5f);
    }
    red[tid] = acc; __syncthreads();
    for (int o = 128; o; o >>= 1) { if (tid < o) red[tid] += red[tid + o]; __syncthreads(); }
    if (tid == 0) g_recon[b] = -red[0];
}

// ---------------- final loss ----------------
__global__ void k_loss(float* __restrict__ out, int loss_idx)
{
    __shared__ float r1[1024];
    __shared__ float r2[1024];
    int t = threadIdx.x;
    r1[t] = g_recon[t]; r2[t] = g_kl[t];
    __syncthreads();
    for (int o = 512; o; o >>= 1) {
        if (t < o) { r1[t] += r1[t + o]; r2[t] += r2[t + o]; }
        __syncthreads();
    }
    if (t == 0) out[loss_idx] = (r1[0] + r2[0]) * (1.0f / (float)Bn);
}

// ---------------- launch ----------------
extern "C" void kernel_launch(void* const* d_in, const int* in_sizes, int n_in,
                              void* d_out, int out_size)
{
    const int*   ids   = (const int*)d_in[0];
    const float* rho   = (const float*)d_in[1];
    const float* alpha = (const float*)d_in[2];
    const float* W1    = (const float*)d_in[3];
    const float* b1    = (const float*)d_in[4];
    const float* Wmu   = (const float*)d_in[5];
    const float* bmu   = (const float*)d_in[6];
    const float* Wlv   = (const float*)d_in[7];
    const float* blv   = (const float*)d_in[8];
    float* out = (float*)d_out;

    static cudaStream_t s2 = nullptr;
    static cudaEvent_t ev_fork = nullptr, ev_join = nullptr, ev_w = nullptr;
    static bool smem_set = false;
    if (!s2) {
        cudaStreamCreateWithFlags(&s2, cudaStreamNonBlocking);
        cudaEventCreateWithFlags(&ev_fork, cudaEventDisableTiming);
        cudaEventCreateWithFlags(&ev_join, cudaEventDisableTiming);
        cudaEventCreateWithFlags(&ev_w, cudaEventDisableTiming);
    }
    if (!smem_set) {
        int smem0 = 2 * 64 * LDK * (int)sizeof(float);
        cudaFuncSetAttribute(k_logits_mma, cudaFuncAttributeMaxDynamicSharedMemorySize, smem0);
        cudaFuncSetAttribute(k_hgemm_mma, cudaFuncAttributeMaxDynamicSharedMemorySize, smem0);
        cudaFuncSetAttribute(k_head_mma, cudaFuncAttributeMaxDynamicSharedMemorySize, smem0);
        smem_set = true;
    }
    int smem = 2 * 64 * LDK * sizeof(float);  // 79872 B

    // fork: chain B on s2
    cudaEventRecord(ev_fork, 0);
    cudaStreamWaitEvent(s2, ev_fork, 0);

    // chain B: weight transposes (feed chain A), then logits/softmax stats
    k_transW1<<<dim3(25, 10), 256, 0, s2>>>(W1);
    k_transWhead<<<(128 * KHP + 255) / 256, 256, 0, s2>>>(Wmu, Wlv);
    cudaEventRecord(ev_w, s2);
    k_logits_mma<<<NBLK, 256, smem, s2>>>(alpha, rho);
    k_maxcomb<<<64, 256, 0, s2>>>();
    k_beta_exp<<<NEXP, 256, 0, s2>>>();
    k_sumcomb<<<64, 256, 0, s2>>>();
    cudaEventRecord(ev_join, s2);

    // chain A: gather -> h-gemm (tf32) -> head (tf32)           (default stream)
    k_gather<<<Bn, 320>>>(ids, rho);
    cudaStreamWaitEvent(0, ev_w, 0);
    k_hgemm_mma<<<dim3(13, 16), 256, smem>>>(b1);
    k_head_mma<<<dim3(2, 16), 256, smem>>>(bmu, blv);

    // join: theta_kl needs mu/lv (A) and rinv (B)
    cudaStreamWaitEvent(0, ev_join, 0);
    k_theta_kl<<<Bn, 64>>>(out);
    k_recon<<<Bn, 256>>>(ids);
    k_loss<<<1, 1024>>>(out, out_size - 1);
}

// round 15
// speedup vs baseline: 1.0712x; 1.0712x over previous
#include <cuda_runtime.h>
#include <math.h>

#define Bn 1024
#define Sn 512
#define Vn 50000
#define En 300
#define Hn 800
#define Tn 50
#define NBLK 782           // ceil(50000/64) mma blocks
#define NEXP 196           // exp-pass blocks
#define KCH 152
#define LDK 156
#define KHP 912            // head K padded (6 * 152)

// ---------------- scratch (device globals; no allocation) ----------------
__device__ __align__(16) float g_x[Bn * En];
__device__ __align__(16) float g_h[Bn * Hn];
__device__ __align__(16) float g_W1T[Hn * 304];          // W1 transposed, K padded to 304
__device__ __align__(16) float g_WheadT[128 * KHP];      // [Wmu|Wlv]^T, K padded to 912
__device__ float g_mu[Bn * Tn];
__device__ float g_lv[Bn * Tn];
__device__ __align__(16) float g_betaT[(size_t)Vn * 64]; // logitsT -> e (unnormalized beta)
__device__ float g_bmax[NBLK * 64];
__device__ float g_bsum[NEXP * 64];
__device__ float g_rmax[64];
__device__ float g_rinv[64];
__device__ float g_thetaS[Bn * 64];
__device__ float g_recon[Bn];
__device__ float g_kl[Bn];

// ---------------- kernel 1: x[b,:] = (1/cnt) * sum_valid rho[id,:] ----------------
// R13-proven: 4 token-groups x 75 threads, ILP-4 float4 loads.
__global__ void k_gather(const int* __restrict__ ids, const float* __restrict__ rho)
{
    __shared__ __align__(16) int sid[Sn];
    __shared__ __align__(16) float sx[4][304];
    __shared__ float s_inv;
    int b = blockIdx.x, tid = threadIdx.x;  // 320 threads
    for (int i = tid; i < Sn; i += 320) {
        int v = ids[b * Sn + i];
        sid[i] = (v == 1 || v == 2) ? -1 : v;
    }
    __syncthreads();
    if (tid < 32) {
        int c = 0;
        for (int i = tid; i < Sn; i += 32) c += (sid[i] >= 0);
#pragma unroll
        for (int o = 16; o; o >>= 1) c += __shfl_down_sync(0xffffffffu, c, o);
        if (tid == 0) s_inv = 1.0f / (float)c;
    }
    __syncthreads();
    if (tid < 300) {
        int g = tid / 75;
        int d = tid % 75;
        const float4* R = reinterpret_cast<const float4*>(rho);
        float4 a0 = {0,0,0,0}, a1 = {0,0,0,0}, a2 = {0,0,0,0}, a3 = {0,0,0,0};
        const int* sg = sid + g;
#pragma unroll 1
        for (int i = 0; i < 128; i += 4) {
            int v0 = sg[4 * (i + 0)];
            int v1 = sg[4 * (i + 1)];
            int v2 = sg[4 * (i + 2)];
            int v3 = sg[4 * (i + 3)];
            if (v0 >= 0) { float4 f = __ldg(&R[(size_t)v0 * 75 + d]); a0.x += f.x; a0.y += f.y; a0.z += f.z; a0.w += f.w; }
            if (v1 >= 0) { float4 f = __ldg(&R[(size_t)v1 * 75 + d]); a1.x += f.x; a1.y += f.y; a1.z += f.z; a1.w += f.w; }
            if (v2 >= 0) { float4 f = __ldg(&R[(size_t)v2 * 75 + d]); a2.x += f.x; a2.y += f.y; a2.z += f.z; a2.w += f.w; }
            if (v3 >= 0) { float4 f = __ldg(&R[(size_t)v3 * 75 + d]); a3.x += f.x; a3.y += f.y; a3.z += f.z; a3.w += f.w; }
        }
        float4 acc;
        acc.x = (a0.x + a1.x) + (a2.x + a3.x);
        acc.y = (a0.y + a1.y) + (a2.y + a3.y);
        acc.z = (a0.z + a1.z) + (a2.z + a3.z);
        acc.w = (a0.w + a1.w) + (a2.w + a3.w);
        *reinterpret_cast<float4*>(&sx[g][4 * d]) = acc;
    }
    __syncthreads();
    if (tid < 300) {
        float r = (sx[0][tid] + sx[1][tid]) + (sx[2][tid] + sx[3][tid]);
        g_x[b * En + tid] = r * s_inv;
    }
}

// ---------------- W1 [300][800] -> W1T [800][304] (zero-padded K) ----------------
__global__ void k_transW1(const float* __restrict__ W1)
{
    __shared__ float tile[32][33];
    int kb = blockIdx.y * 32, nb = blockIdx.x * 32;
    int tx = threadIdx.x & 31, ty = threadIdx.x >> 5;
#pragma unroll
    for (int i = 0; i < 32; i += 8) {
        int k = kb + ty + i, n = nb + tx;
        tile[ty + i][tx] = (k < En && n < Hn) ? W1[k * Hn + n] : 0.f;
    }
    __syncthreads();
#pragma unroll
    for (int i = 0; i < 32; i += 8) {
        int n = nb + ty + i, k = kb + tx;
        if (n < Hn && k < 304) g_W1T[n * 304 + k] = tile[tx][ty + i];
    }
}

// ---------------- [Wmu|Wlv] -> WheadT [128][912] ----------------
__global__ void k_transWhead(const float* __restrict__ Wmu, const float* __restrict__ Wlv)
{
    int idx = blockIdx.x * 256 + threadIdx.x;
    if (idx < 128 * KHP) {
        int c = idx / KHP, k = idx % KHP;
        float v = 0.f;
        if (k < Hn) {
            if (c < 50)       v = Wmu[k * Tn + c];
            else if (c < 100) v = Wlv[k * Tn + (c - 50)];
        }
        g_WheadT[idx] = v;
    }
}

// ---------------- h = relu(x @ W1 + b1) via tf32 mma ----------------
__global__ void k_hgemm_mma(const float* __restrict__ b1)
{
    extern __shared__ float sm[];
    float* As = sm;
    float* Bs = sm + 64 * LDK;
    int tid = threadIdx.x;
    int lane = tid & 31, warp = tid >> 5;
    int gid = lane >> 2, tig = lane & 3;
    int wm = warp >> 1, wn = warp & 1;
    int m0 = blockIdx.y * 64, n0 = blockIdx.x * 64;
    float c[4][4] = {};

    for (int ch = 0; ch < 2; ch++) {
        int kbase = ch * KCH;
        __syncthreads();
        for (int i = tid; i < 64 * 39; i += 256) {
            int row = i / 39, q = i % 39;
            int col = q * 4;
            int gk = kbase + col;
            float4 v = make_float4(0.f, 0.f, 0.f, 0.f);
            if (q < 38 && gk < En)
                v = *reinterpret_cast<const float4*>(&g_x[(size_t)(m0 + row) * En + gk]);
            unsigned t0, t1, t2, t3;
            asm("cvt.rna.tf32.f32 %0, %1;" : "=r"(t0) : "f"(v.x));
            asm("cvt.rna.tf32.f32 %0, %1;" : "=r"(t1) : "f"(v.y));
            asm("cvt.rna.tf32.f32 %0, %1;" : "=r"(t2) : "f"(v.z));
            asm("cvt.rna.tf32.f32 %0, %1;" : "=r"(t3) : "f"(v.w));
            *reinterpret_cast<float4*>(&As[row * LDK + col]) =
                make_float4(__uint_as_float(t0), __uint_as_float(t1),
                            __uint_as_float(t2), __uint_as_float(t3));
        }
        for (int i = tid; i < 64 * 39; i += 256) {
            int row = i / 39, q = i % 39;
            int col = q * 4;
            int gk = kbase + col;
            int n = n0 + row;
            float4 x = make_float4(0.f, 0.f, 0.f, 0.f);
            if (q < 38 && n < Hn)
                x = *reinterpret_cast<const float4*>(&g_W1T[(size_t)n * 304 + gk]);
            unsigned t0, t1, t2, t3;
            asm("cvt.rna.tf32.f32 %0, %1;" : "=r"(t0) : "f"(x.x));
            asm("cvt.rna.tf32.f32 %0, %1;" : "=r"(t1) : "f"(x.y));
            asm("cvt.rna.tf32.f32 %0, %1;" : "=r"(t2) : "f"(x.z));
            asm("cvt.rna.tf32.f32 %0, %1;" : "=r"(t3) : "f"(x.w));
            *reinterpret_cast<float4*>(&Bs[row * LDK + col]) =
                make_float4(__uint_as_float(t0), __uint_as_float(t1),
                            __uint_as_float(t2), __uint_as_float(t3));
        }
        __syncthreads();

        const float* Ap = As + (wm * 16 + gid) * LDK + tig;
#pragma unroll
        for (int ks = 0; ks < 19; ks++) {
            int k = ks * 8;
            unsigned a0 = __float_as_uint(Ap[k]);
            unsigned a1 = __float_as_uint(Ap[8 * LDK + k]);
            unsigned a2 = __float_as_uint(Ap[k + 4]);
            unsigned a3 = __float_as_uint(Ap[8 * LDK + k + 4]);
#pragma unroll
            for (int nt = 0; nt < 4; nt++) {
                const float* Bp = Bs + (wn * 32 + nt * 8 + gid) * LDK + tig + k;
                unsigned b0 = __float_as_uint(Bp[0]);
                unsigned b1v = __float_as_uint(Bp[4]);
                asm volatile(
                    "mma.sync.aligned.m16n8k8.row.col.f32.tf32.tf32.f32 "
                    "{%0,%1,%2,%3}, {%4,%5,%6,%7}, {%8,%9}, {%0,%1,%2,%3};"
                    : "+f"(c[nt][0]), "+f"(c[nt][1]), "+f"(c[nt][2]), "+f"(c[nt][3])
                    : "r"(a0), "r"(a1), "r"(a2), "r"(a3), "r"(b0), "r"(b1v));
            }
        }
    }

    int r0 = m0 + wm * 16 + gid;
    int colbase = n0 + wn * 32 + tig * 2;
#pragma unroll
    for (int nt = 0; nt < 4; nt++) {
        int col = colbase + nt * 8;
        if (col < Hn) {
            float bv0 = __ldg(&b1[col]), bv1 = __ldg(&b1[col + 1]);
            float2 o0 = make_float2(fmaxf(c[nt][0] + bv0, 0.f), fmaxf(c[nt][1] + bv1, 0.f));
            float2 o1 = make_float2(fmaxf(c[nt][2] + bv0, 0.f), fmaxf(c[nt][3] + bv1, 0.f));
            *reinterpret_cast<float2*>(&g_h[(size_t)r0 * Hn + col]) = o0;
            *reinterpret_cast<float2*>(&g_h[(size_t)(r0 + 8) * Hn + col]) = o1;
        }
    }
}

// ---------------- mu/lv = h @ [Wmu|Wlv] + bias via tf32 mma ----------------
__global__ void k_head_mma(const float* __restrict__ bmu, const float* __restrict__ blv)
{
    extern __shared__ float sm[];
    float* As = sm;
    float* Bs = sm + 64 * LDK;
    int tid = threadIdx.x;
    int lane = tid & 31, warp = tid >> 5;
    int gid = lane >> 2, tig = lane & 3;
    int wm = warp >> 1, wn = warp & 1;
    int m0 = blockIdx.y * 64, n0 = blockIdx.x * 64;
    float c[4][4] = {};

    for (int ch = 0; ch < 6; ch++) {
        int kbase = ch * KCH;
        __syncthreads();
        for (int i = tid; i < 64 * 39; i += 256) {
            int row = i / 39, q = i % 39;
            int col = q * 4;
            int gk = kbase + col;
            float4 v = make_float4(0.f, 0.f, 0.f, 0.f);
            if (q < 38 && gk < Hn)
                v = *reinterpret_cast<const float4*>(&g_h[(size_t)(m0 + row) * Hn + gk]);
            unsigned t0, t1, t2, t3;
            asm("cvt.rna.tf32.f32 %0, %1;" : "=r"(t0) : "f"(v.x));
            asm("cvt.rna.tf32.f32 %0, %1;" : "=r"(t1) : "f"(v.y));
            asm("cvt.rna.tf32.f32 %0, %1;" : "=r"(t2) : "f"(v.z));
            asm("cvt.rna.tf32.f32 %0, %1;" : "=r"(t3) : "f"(v.w));
            *reinterpret_cast<float4*>(&As[row * LDK + col]) =
                make_float4(__uint_as_float(t0), __uint_as_float(t1),
                            __uint_as_float(t2), __uint_as_float(t3));
        }
        for (int i = tid; i < 64 * 39; i += 256) {
            int row = i / 39, q = i % 39;
            int col = q * 4;
            int gk = kbase + col;
            float4 x = make_float4(0.f, 0.f, 0.f, 0.f);
            if (q < 38)
                x = *reinterpret_cast<const float4*>(&g_WheadT[(size_t)(n0 + row) * KHP + gk]);
            unsigned t0, t1, t2, t3;
            asm("cvt.rna.tf32.f32 %0, %1;" : "=r"(t0) : "f"(x.x));
            asm("cvt.rna.tf32.f32 %0, %1;" : "=r"(t1) : "f"(x.y));
            asm("cvt.rna.tf32.f32 %0, %1;" : "=r"(t2) : "f"(x.z));
            asm("cvt.rna.tf32.f32 %0, %1;" : "=r"(t3) : "f"(x.w));
            *reinterpret_cast<float4*>(&Bs[row * LDK + col]) =
                make_float4(__uint_as_float(t0), __uint_as_float(t1),
                            __uint_as_float(t2), __uint_as_float(t3));
        }
        __syncthreads();

        const float* Ap = As + (wm * 16 + gid) * LDK + tig;
#pragma unroll
        for (int ks = 0; ks < 19; ks++) {
            int k = ks * 8;
            unsigned a0 = __float_as_uint(Ap[k]);
            unsigned a1 = __float_as_uint(Ap[8 * LDK + k]);
            unsigned a2 = __float_as_uint(Ap[k + 4]);
            unsigned a3 = __float_as_uint(Ap[8 * LDK + k + 4]);
#pragma unroll
            for (int nt = 0; nt < 4; nt++) {
                const float* Bp = Bs + (wn * 32 + nt * 8 + gid) * LDK + tig + k;
                unsigned b0 = __float_as_uint(Bp[0]);
                unsigned b1v = __float_as_uint(Bp[4]);
                asm volatile(
                    "mma.sync.aligned.m16n8k8.row.col.f32.tf32.tf32.f32 "
                    "{%0,%1,%2,%3}, {%4,%5,%6,%7}, {%8,%9}, {%0,%1,%2,%3};"
                    : "+f"(c[nt][0]), "+f"(c[nt][1]), "+f"(c[nt][2]), "+f"(c[nt][3])
                    : "r"(a0), "r"(a1), "r"(a2), "r"(a3), "r"(b0), "r"(b1v));
            }
        }
    }

    int r0 = m0 + wm * 16 + gid;
    int colbase = n0 + wn * 32 + tig * 2;
#pragma unroll
    for (int nt = 0; nt < 4; nt++) {
#pragma unroll
        for (int j = 0; j < 2; j++) {
            int col = colbase + nt * 8 + j;
            float v0 = c[nt][j], v1 = c[nt][2 + j];
            if (col < 50) {
                float bb = __ldg(&bmu[col]);
                g_mu[(size_t)r0 * Tn + col] = v0 + bb;
                g_mu[(size_t)(r0 + 8) * Tn + col] = v1 + bb;
            } else if (col < 100) {
                float bb = __ldg(&blv[col - 50]);
                g_lv[(size_t)r0 * Tn + (col - 50)] = v0 + bb;
                g_lv[(size_t)(r0 + 8) * Tn + (col - 50)] = v1 + bb;
            }
        }
    }
}

// ---------------- logitsT[v][64] via tf32 mma + fused transpose + max partials -------
__global__ void k_logits_mma(const float* __restrict__ alpha, const float* __restrict__ rho)
{
    extern __shared__ float sm[];
    float* As = sm;
    float* Bs = sm + 64 * LDK;
    __shared__ float pmax[2][64];
    int tid = threadIdx.x;
    int lane = tid & 31, warp = tid >> 5;
    int gid = lane >> 2, tig = lane & 3;
    int wm = warp >> 1, wn = warp & 1;
    int v0 = blockIdx.x * 64;
    float c[4][4] = {};

    for (int ch = 0; ch < 2; ch++) {
        int kbase = ch * KCH;
        __syncthreads();
        for (int i = tid; i < 64 * 39; i += 256) {
            int row = i / 39, q = i % 39;
            int col = q * 4;
            int gk = kbase + col;
            float4 v = make_float4(0.f, 0.f, 0.f, 0.f);
            if (q < 38 && row < Tn && gk < En)
                v = *reinterpret_cast<const float4*>(&alpha[(size_t)row * En + gk]);
            unsigned t0, t1, t2, t3;
            asm("cvt.rna.tf32.f32 %0, %1;" : "=r"(t0) : "f"(v.x));
            asm("cvt.rna.tf32.f32 %0, %1;" : "=r"(t1) : "f"(v.y));
            asm("cvt.rna.tf32.f32 %0, %1;" : "=r"(t2) : "f"(v.z));
            asm("cvt.rna.tf32.f32 %0, %1;" : "=r"(t3) : "f"(v.w));
            *reinterpret_cast<float4*>(&As[row * LDK + col]) =
                make_float4(__uint_as_float(t0), __uint_as_float(t1),
                            __uint_as_float(t2), __uint_as_float(t3));
        }
        for (int i = tid; i < 64 * 39; i += 256) {
            int row = i / 39, q = i % 39;
            int col = q * 4;
            int gk = kbase + col;
            int v = v0 + row;
            float4 x = make_float4(0.f, 0.f, 0.f, 0.f);
            if (q < 38 && v < Vn && gk < En)
                x = *reinterpret_cast<const float4*>(&rho[(size_t)v * En + gk]);
            unsigned t0, t1, t2, t3;
            asm("cvt.rna.tf32.f32 %0, %1;" : "=r"(t0) : "f"(x.x));
            asm("cvt.rna.tf32.f32 %0, %1;" : "=r"(t1) : "f"(x.y));
            asm("cvt.rna.tf32.f32 %0, %1;" : "=r"(t2) : "f"(x.z));
            asm("cvt.rna.tf32.f32 %0, %1;" : "=r"(t3) : "f"(x.w));
            *reinterpret_cast<float4*>(&Bs[row * LDK + col]) =
                make_float4(__uint_as_float(t0), __uint_as_float(t1),
                            __uint_as_float(t2), __uint_as_float(t3));
        }
        __syncthreads();

        const float* Ap = As + (wm * 16 + gid) * LDK + tig;
#pragma unroll
        for (int ks = 0; ks < 19; ks++) {
            int k = ks * 8;
            unsigned a0 = __float_as_uint(Ap[k]);
            unsigned a1 = __float_as_uint(Ap[8 * LDK + k]);
            unsigned a2 = __float_as_uint(Ap[k + 4]);
            unsigned a3 = __float_as_uint(Ap[8 * LDK + k + 4]);
#pragma unroll
            for (int nt = 0; nt < 4; nt++) {
                const float* Bp = Bs + (wn * 32 + nt * 8 + gid) * LDK + tig + k;
                unsigned b0 = __float_as_uint(Bp[0]);
                unsigned b1 = __float_as_uint(Bp[4]);
                asm volatile(
                    "mma.sync.aligned.m16n8k8.row.col.f32.tf32.tf32.f32 "
                    "{%0,%1,%2,%3}, {%4,%5,%6,%7}, {%8,%9}, {%0,%1,%2,%3};"
                    : "+f"(c[nt][0]), "+f"(c[nt][1]), "+f"(c[nt][2]), "+f"(c[nt][3])
                    : "r"(a0), "r"(a1), "r"(a2), "r"(a3), "r"(b0), "r"(b1));
            }
        }
    }

    int colbase = v0 + wn * 32 + tig * 2;
    float m0 = -1e30f, m1 = -1e30f;
#pragma unroll
    for (int nt = 0; nt < 4; nt++) {
        int cA = colbase + nt * 8;
        if (cA < Vn)     { m0 = fmaxf(m0, c[nt][0]); m1 = fmaxf(m1, c[nt][2]); }
        if (cA + 1 < Vn) { m0 = fmaxf(m0, c[nt][1]); m1 = fmaxf(m1, c[nt][3]); }
    }
    m0 = fmaxf(m0, __shfl_xor_sync(0xffffffffu, m0, 1));
    m0 = fmaxf(m0, __shfl_xor_sync(0xffffffffu, m0, 2));
    m1 = fmaxf(m1, __shfl_xor_sync(0xffffffffu, m1, 1));
    m1 = fmaxf(m1, __shfl_xor_sync(0xffffffffu, m1, 2));
    if (tig == 0) {
        pmax[wn][wm * 16 + gid]     = m0;
        pmax[wn][wm * 16 + gid + 8] = m1;
    }
    __syncthreads();
    if (tid < 64)
        g_bmax[blockIdx.x * 64 + tid] = fmaxf(pmax[0][tid], pmax[1][tid]);

    float* sT = sm;  // [64][65]
#pragma unroll
    for (int nt = 0; nt < 4; nt++) {
        int vl = wn * 32 + nt * 8 + tig * 2;
        int r = wm * 16 + gid;
        sT[vl * 65 + r]           = c[nt][0];
        sT[(vl + 1) * 65 + r]     = c[nt][1];
        sT[vl * 65 + r + 8]       = c[nt][2];
        sT[(vl + 1) * 65 + r + 8] = c[nt][3];
    }
    __syncthreads();
#pragma unroll
    for (int rep = 0; rep < 16; rep++) {
        int idx = rep * 256 + tid;
        int vl = idx >> 6, t = idx & 63;
        int v = v0 + vl;
        if (v < Vn) g_betaT[(size_t)v * 64 + t] = sT[vl * 65 + t];
    }
}

// ---------------- combine max partials (grid 64) ----------------
__global__ void k_maxcomb()
{
    __shared__ float red[256];
    int t = blockIdx.x, tid = threadIdx.x;
    float m = -1e30f;
#pragma unroll 4
    for (int i = tid; i < NBLK; i += 256) m = fmaxf(m, g_bmax[i * 64 + t]);
    red[tid] = m; __syncthreads();
    for (int o = 128; o; o >>= 1) {
        if (tid < o) red[tid] = fmaxf(red[tid], red[tid + o]);
        __syncthreads();
    }
    if (tid == 0) g_rmax[t] = red[0];
}

// ---------------- exp in place + sum partials ----------------
__global__ void k_beta_exp()
{
    __shared__ float srmax[64];
    __shared__ float ssum[16][64];
    int tid = threadIdx.x;
    if (tid < 64) srmax[tid] = g_rmax[tid];
    __syncthreads();
    float4* P = reinterpret_cast<float4*>(g_betaT);
    size_t base = (size_t)blockIdx.x * 4096;
    int t0 = (tid & 15) * 4;
    float rm0 = srmax[t0], rm1 = srmax[t0 + 1], rm2 = srmax[t0 + 2], rm3 = srmax[t0 + 3];
    float s0 = 0.f, s1 = 0.f, s2 = 0.f, s3 = 0.f;
#pragma unroll
    for (int k = 0; k < 16; k++) {
        size_t idx = base + (size_t)k * 256 + tid;
        if (idx < (size_t)Vn * 16) {
            float4 x = P[idx];
            x.x = expf(x.x - rm0);
            x.y = expf(x.y - rm1);
            x.z = expf(x.z - rm2);
            x.w = expf(x.w - rm3);
            s0 += x.x; s1 += x.y; s2 += x.z; s3 += x.w;
            P[idx] = x;
        }
    }
    int g = tid >> 4;
    ssum[g][t0 + 0] = s0; ssum[g][t0 + 1] = s1;
    ssum[g][t0 + 2] = s2; ssum[g][t0 + 3] = s3;
    __syncthreads();
    if (tid < 64) {
        float s = 0.f;
#pragma unroll
        for (int i = 0; i < 16; i++) s += ssum[i][tid];
        g_bsum[blockIdx.x * 64 + tid] = s;
    }
}

// ---------------- combine sum partials -> rinv (grid 64) ----------------
__global__ void k_sumcomb()
{
    __shared__ float red[256];
    int t = blockIdx.x, tid = threadIdx.x;
    float s = 0.f;
    if (tid < NEXP) s = g_bsum[tid * 64 + t];
    red[tid] = s; __syncthreads();
    for (int o = 128; o; o >>= 1) {
        if (tid < o) red[tid] += red[tid + o];
        __syncthreads();
    }
    if (tid == 0) g_rinv[t] = 1.0f / red[0];
}

// ---------------- kl + theta softmax (+ scaled theta for recon) ----------------
__global__ void k_theta_kl(float* __restrict__ out)
{
    int b = blockIdx.x, t = threadIdx.x;
    __shared__ float red[64];
    bool ok = (t < Tn);
    float mu = 0.f, lv = 0.f;
    if (ok) { mu = g_mu[b * Tn + t]; lv = g_lv[b * Tn + t]; }
    float kle = ok ? (1.f + lv - mu * mu - expf(lv)) : 0.f;
    red[t] = kle; __syncthreads();
    for (int o = 32; o; o >>= 1) { if (t < o) red[t] += red[t + o]; __syncthreads(); }
    if (t == 0) g_kl[b] = -0.5f * red[0];
    __syncthreads();
    red[t] = ok ? mu : -1e30f; __syncthreads();
    for (int o = 32; o; o >>= 1) { if (t < o) red[t] = fmaxf(red[t], red[t + o]); __syncthreads(); }
    float mx = red[0]; __syncthreads();
    float e = ok ? expf(mu - mx) : 0.f;
    red[t] = e; __syncthreads();
    for (int o = 32; o; o >>= 1) { if (t < o) red[t] += red[t + o]; __syncthreads(); }
    float inv = 1.0f / red[0];
    float th = e * inv;
    if (ok) out[b * Tn + t] = th;
    g_thetaS[b * 64 + t] = ok ? th * g_rinv[t] : 0.f;
}

// ---------------- recon: 13 float4 per token (th[52..63]=0, exact) ----------------
__global__ void k_recon(const int* __restrict__ ids)
{
    __shared__ float th[64];
    __shared__ float red[256];
    int b = blockIdx.x, tid = threadIdx.x;
    if (tid < 64) th[tid] = g_thetaS[b * 64 + tid];
    __syncthreads();
    float acc = 0.f;
#pragma unroll 1
    for (int s = tid; s < Sn; s += 256) {
        int v = ids[b * Sn + s];
        if (v == 1 || v == 2) continue;
        const float4* p = reinterpret_cast<const float4*>(g_betaT + (size_t)v * 64);
        float d = 0.f;
#pragma unroll
        for (int i = 0; i < 13; i++) {
            float4 bv = p[i];
            float4 tv = *reinterpret_cast<const float4*>(&th[i * 4]);
            d += bv.x*tv.x + bv.y*tv.y + bv.z*tv.z + bv.w*tv.w;
        }
        acc += logf(d + 1e-5f);
    }
    red[tid] = acc; __syncthreads();
    for (int o = 128; o; o >>= 1) { if (tid < o) red[tid] += red[tid + o]; __syncthreads(); }
    if (tid == 0) g_recon[b] = -red[0];
}

// ---------------- final loss ----------------
__global__ void k_loss(float* __restrict__ out, int loss_idx)
{
    __shared__ float r1[1024];
    __shared__ float r2[1024];
    int t = threadIdx.x;
    r1[t] = g_recon[t]; r2[t] = g_kl[t];
    __syncthreads();
    for (int o = 512; o; o >>= 1) {
        if (t < o) { r1[t] += r1[t + o]; r2[t] += r2[t + o]; }
        __syncthreads();
    }
    if (t == 0) out[loss_idx] = (r1[0] + r2[0]) * (1.0f / (float)Bn);
}

// ---------------- launch ----------------
extern "C" void kernel_launch(void* const* d_in, const int* in_sizes, int n_in,
                              void* d_out, int out_size)
{
    const int*   ids   = (const int*)d_in[0];
    const float* rho   = (const float*)d_in[1];
    const float* alpha = (const float*)d_in[2];
    const float* W1    = (const float*)d_in[3];
    const float* b1    = (const float*)d_in[4];
    const float* Wmu   = (const float*)d_in[5];
    const float* bmu   = (const float*)d_in[6];
    const float* Wlv   = (const float*)d_in[7];
    const float* blv   = (const float*)d_in[8];
    float* out = (float*)d_out;

    static cudaStream_t s2 = nullptr;
    static cudaEvent_t ev_fork = nullptr, ev_join = nullptr, ev_w = nullptr;
    static bool smem_set = false;
    if (!s2) {
        cudaStreamCreateWithFlags(&s2, cudaStreamNonBlocking);
        cudaEventCreateWithFlags(&ev_fork, cudaEventDisableTiming);
        cudaEventCreateWithFlags(&ev_join, cudaEventDisableTiming);
        cudaEventCreateWithFlags(&ev_w, cudaEventDisableTiming);
    }
    if (!smem_set) {
        int smem0 = 2 * 64 * LDK * (int)sizeof(float);
        cudaFuncSetAttribute(k_logits_mma, cudaFuncAttributeMaxDynamicSharedMemorySize, smem0);
        cudaFuncSetAttribute(k_hgemm_mma, cudaFuncAttributeMaxDynamicSharedMemorySize, smem0);
        cudaFuncSetAttribute(k_head_mma, cudaFuncAttributeMaxDynamicSharedMemorySize, smem0);
        smem_set = true;
    }
    int smem = 2 * 64 * LDK * sizeof(float);  // 79872 B

    // fork: chain B on s2
    cudaEventRecord(ev_fork, 0);
    cudaStreamWaitEvent(s2, ev_fork, 0);

    // chain B: weight transposes (feed chain A), then logits/softmax stats
    k_transW1<<<dim3(25, 10), 256, 0, s2>>>(W1);
    k_transWhead<<<(128 * KHP + 255) / 256, 256, 0, s2>>>(Wmu, Wlv);
    cudaEventRecord(ev_w, s2);
    k_logits_mma<<<NBLK, 256, smem, s2>>>(alpha, rho);
    k_maxcomb<<<64, 256, 0, s2>>>();
    k_beta_exp<<<NEXP, 256, 0, s2>>>();
    k_sumcomb<<<64, 256, 0, s2>>>();
    cudaEventRecord(ev_join, s2);

    // chain A: gather -> h-gemm (tf32) -> head (tf32)           (default stream)
    k_gather<<<Bn, 320>>>(ids, rho);
    cudaStreamWaitEvent(0, ev_w, 0);
    k_hgemm_mma<<<dim3(13, 16), 256, smem>>>(b1);
    k_head_mma<<<dim3(2, 16), 256, smem>>>(bmu, blv);

    // join: theta_kl needs mu/lv (A) and rinv (B)
    cudaStreamWaitEvent(0, ev_join, 0);
    k_theta_kl<<<Bn, 64>>>(out);
    k_recon<<<Bn, 256>>>(ids);
    k_loss<<<1, 1024>>>(out, out_size - 1);
}

// round 16
// speedup vs baseline: 1.0807x; 1.0089x over previous
#include <cuda_runtime.h>
#include <math.h>

#define Bn 1024
#define Sn 512
#define Vn 50000
#define En 300
#define Hn 800
#define Tn 50
#define NBLK 782           // ceil(50000/64) mma blocks
#define NEXP 196           // exp-pass blocks
#define KCH 152
#define LDK 156
#define KHP 912            // head K padded (6 * 152)

// ---------------- scratch (device globals; no allocation) ----------------
__device__ __align__(16) float g_x[Bn * En];
__device__ __align__(16) float g_h[Bn * Hn];
__device__ __align__(16) float g_W1T[Hn * 304];
__device__ __align__(16) float g_WheadT[128 * KHP];
__device__ float g_mu[Bn * Tn];
__device__ float g_lv[Bn * Tn];
__device__ __align__(16) float g_betaT[(size_t)Vn * 64];
__device__ float g_bmax[NBLK * 64];
__device__ float g_bsum[NEXP * 64];
__device__ float g_rmax[64];
__device__ float g_rinv[64];
__device__ __align__(16) float g_theta[Bn * 64];   // UNSCALED theta (padded, t>=50 zero)
__device__ float g_recon[Bn];
__device__ float g_kl[Bn];

// ---------------- kernel 1: x[b,:] = (1/cnt) * sum_valid rho[id,:] ----------------
__global__ void k_gather(const int* __restrict__ ids, const float* __restrict__ rho)
{
    __shared__ __align__(16) int sid[Sn];
    __shared__ __align__(16) float sx[4][304];
    __shared__ float s_inv;
    int b = blockIdx.x, tid = threadIdx.x;  // 320 threads
    for (int i = tid; i < Sn; i += 320) {
        int v = ids[b * Sn + i];
        sid[i] = (v == 1 || v == 2) ? -1 : v;
    }
    __syncthreads();
    if (tid < 32) {
        int c = 0;
        for (int i = tid; i < Sn; i += 32) c += (sid[i] >= 0);
#pragma unroll
        for (int o = 16; o; o >>= 1) c += __shfl_down_sync(0xffffffffu, c, o);
        if (tid == 0) s_inv = 1.0f / (float)c;
    }
    __syncthreads();
    if (tid < 300) {
        int g = tid / 75;
        int d = tid % 75;
        const float4* R = reinterpret_cast<const float4*>(rho);
        float4 a0 = {0,0,0,0}, a1 = {0,0,0,0}, a2 = {0,0,0,0}, a3 = {0,0,0,0};
        const int* sg = sid + g;
#pragma unroll 1
        for (int i = 0; i < 128; i += 4) {
            int v0 = sg[4 * (i + 0)];
            int v1 = sg[4 * (i + 1)];
            int v2 = sg[4 * (i + 2)];
            int v3 = sg[4 * (i + 3)];
            if (v0 >= 0) { float4 f = __ldg(&R[(size_t)v0 * 75 + d]); a0.x += f.x; a0.y += f.y; a0.z += f.z; a0.w += f.w; }
            if (v1 >= 0) { float4 f = __ldg(&R[(size_t)v1 * 75 + d]); a1.x += f.x; a1.y += f.y; a1.z += f.z; a1.w += f.w; }
            if (v2 >= 0) { float4 f = __ldg(&R[(size_t)v2 * 75 + d]); a2.x += f.x; a2.y += f.y; a2.z += f.z; a2.w += f.w; }
            if (v3 >= 0) { float4 f = __ldg(&R[(size_t)v3 * 75 + d]); a3.x += f.x; a3.y += f.y; a3.z += f.z; a3.w += f.w; }
        }
        float4 acc;
        acc.x = (a0.x + a1.x) + (a2.x + a3.x);
        acc.y = (a0.y + a1.y) + (a2.y + a3.y);
        acc.z = (a0.z + a1.z) + (a2.z + a3.z);
        acc.w = (a0.w + a1.w) + (a2.w + a3.w);
        *reinterpret_cast<float4*>(&sx[g][4 * d]) = acc;
    }
    __syncthreads();
    if (tid < 300) {
        float r = (sx[0][tid] + sx[1][tid]) + (sx[2][tid] + sx[3][tid]);
        g_x[b * En + tid] = r * s_inv;
    }
}

// ---------------- W1 [300][800] -> W1T [800][304] ----------------
__global__ void k_transW1(const float* __restrict__ W1)
{
    __shared__ float tile[32][33];
    int kb = blockIdx.y * 32, nb = blockIdx.x * 32;
    int tx = threadIdx.x & 31, ty = threadIdx.x >> 5;
#pragma unroll
    for (int i = 0; i < 32; i += 8) {
        int k = kb + ty + i, n = nb + tx;
        tile[ty + i][tx] = (k < En && n < Hn) ? W1[k * Hn + n] : 0.f;
    }
    __syncthreads();
#pragma unroll
    for (int i = 0; i < 32; i += 8) {
        int n = nb + ty + i, k = kb + tx;
        if (n < Hn && k < 304) g_W1T[n * 304 + k] = tile[tx][ty + i];
    }
}

// ---------------- [Wmu|Wlv] -> WheadT [128][912] ----------------
__global__ void k_transWhead(const float* __restrict__ Wmu, const float* __restrict__ Wlv)
{
    int idx = blockIdx.x * 256 + threadIdx.x;
    if (idx < 128 * KHP) {
        int c = idx / KHP, k = idx % KHP;
        float v = 0.f;
        if (k < Hn) {
            if (c < 50)       v = Wmu[k * Tn + c];
            else if (c < 100) v = Wlv[k * Tn + (c - 50)];
        }
        g_WheadT[idx] = v;
    }
}

// ---------------- h = relu(x @ W1 + b1) via tf32 mma ----------------
__global__ void k_hgemm_mma(const float* __restrict__ b1)
{
    extern __shared__ float sm[];
    float* As = sm;
    float* Bs = sm + 64 * LDK;
    int tid = threadIdx.x;
    int lane = tid & 31, warp = tid >> 5;
    int gid = lane >> 2, tig = lane & 3;
    int wm = warp >> 1, wn = warp & 1;
    int m0 = blockIdx.y * 64, n0 = blockIdx.x * 64;
    float c[4][4] = {};

    for (int ch = 0; ch < 2; ch++) {
        int kbase = ch * KCH;
        __syncthreads();
        for (int i = tid; i < 64 * 39; i += 256) {
            int row = i / 39, q = i % 39;
            int col = q * 4;
            int gk = kbase + col;
            float4 v = make_float4(0.f, 0.f, 0.f, 0.f);
            if (q < 38 && gk < En)
                v = *reinterpret_cast<const float4*>(&g_x[(size_t)(m0 + row) * En + gk]);
            unsigned t0, t1, t2, t3;
            asm("cvt.rna.tf32.f32 %0, %1;" : "=r"(t0) : "f"(v.x));
            asm("cvt.rna.tf32.f32 %0, %1;" : "=r"(t1) : "f"(v.y));
            asm("cvt.rna.tf32.f32 %0, %1;" : "=r"(t2) : "f"(v.z));
            asm("cvt.rna.tf32.f32 %0, %1;" : "=r"(t3) : "f"(v.w));
            *reinterpret_cast<float4*>(&As[row * LDK + col]) =
                make_float4(__uint_as_float(t0), __uint_as_float(t1),
                            __uint_as_float(t2), __uint_as_float(t3));
        }
        for (int i = tid; i < 64 * 39; i += 256) {
            int row = i / 39, q = i % 39;
            int col = q * 4;
            int gk = kbase + col;
            int n = n0 + row;
            float4 x = make_float4(0.f, 0.f, 0.f, 0.f);
            if (q < 38 && n < Hn)
                x = *reinterpret_cast<const float4*>(&g_W1T[(size_t)n * 304 + gk]);
            unsigned t0, t1, t2, t3;
            asm("cvt.rna.tf32.f32 %0, %1;" : "=r"(t0) : "f"(x.x));
            asm("cvt.rna.tf32.f32 %0, %1;" : "=r"(t1) : "f"(x.y));
            asm("cvt.rna.tf32.f32 %0, %1;" : "=r"(t2) : "f"(x.z));
            asm("cvt.rna.tf32.f32 %0, %1;" : "=r"(t3) : "f"(x.w));
            *reinterpret_cast<float4*>(&Bs[row * LDK + col]) =
                make_float4(__uint_as_float(t0), __uint_as_float(t1),
                            __uint_as_float(t2), __uint_as_float(t3));
        }
        __syncthreads();

        const float* Ap = As + (wm * 16 + gid) * LDK + tig;
#pragma unroll
        for (int ks = 0; ks < 19; ks++) {
            int k = ks * 8;
            unsigned a0 = __float_as_uint(Ap[k]);
            unsigned a1 = __float_as_uint(Ap[8 * LDK + k]);
            unsigned a2 = __float_as_uint(Ap[k + 4]);
            unsigned a3 = __float_as_uint(Ap[8 * LDK + k + 4]);
#pragma unroll
            for (int nt = 0; nt < 4; nt++) {
                const float* Bp = Bs + (wn * 32 + nt * 8 + gid) * LDK + tig + k;
                unsigned b0 = __float_as_uint(Bp[0]);
                unsigned b1v = __float_as_uint(Bp[4]);
                asm volatile(
                    "mma.sync.aligned.m16n8k8.row.col.f32.tf32.tf32.f32 "
                    "{%0,%1,%2,%3}, {%4,%5,%6,%7}, {%8,%9}, {%0,%1,%2,%3};"
                    : "+f"(c[nt][0]), "+f"(c[nt][1]), "+f"(c[nt][2]), "+f"(c[nt][3])
                    : "r"(a0), "r"(a1), "r"(a2), "r"(a3), "r"(b0), "r"(b1v));
            }
        }
    }

    int r0 = m0 + wm * 16 + gid;
    int colbase = n0 + wn * 32 + tig * 2;
#pragma unroll
    for (int nt = 0; nt < 4; nt++) {
        int col = colbase + nt * 8;
        if (col < Hn) {
            float bv0 = __ldg(&b1[col]), bv1 = __ldg(&b1[col + 1]);
            float2 o0 = make_float2(fmaxf(c[nt][0] + bv0, 0.f), fmaxf(c[nt][1] + bv1, 0.f));
            float2 o1 = make_float2(fmaxf(c[nt][2] + bv0, 0.f), fmaxf(c[nt][3] + bv1, 0.f));
            *reinterpret_cast<float2*>(&g_h[(size_t)r0 * Hn + col]) = o0;
            *reinterpret_cast<float2*>(&g_h[(size_t)(r0 + 8) * Hn + col]) = o1;
        }
    }
}

// ---------------- mu/lv = h @ [Wmu|Wlv] + bias via tf32 mma ----------------
__global__ void k_head_mma(const float* __restrict__ bmu, const float* __restrict__ blv)
{
    extern __shared__ float sm[];
    float* As = sm;
    float* Bs = sm + 64 * LDK;
    int tid = threadIdx.x;
    int lane = tid & 31, warp = tid >> 5;
    int gid = lane >> 2, tig = lane & 3;
    int wm = warp >> 1, wn = warp & 1;
    int m0 = blockIdx.y * 64, n0 = blockIdx.x * 64;
    float c[4][4] = {};

    for (int ch = 0; ch < 6; ch++) {
        int kbase = ch * KCH;
        __syncthreads();
        for (int i = tid; i < 64 * 39; i += 256) {
            int row = i / 39, q = i % 39;
            int col = q * 4;
            int gk = kbase + col;
            float4 v = make_float4(0.f, 0.f, 0.f, 0.f);
            if (q < 38 && gk < Hn)
                v = *reinterpret_cast<const float4*>(&g_h[(size_t)(m0 + row) * Hn + gk]);
            unsigned t0, t1, t2, t3;
            asm("cvt.rna.tf32.f32 %0, %1;" : "=r"(t0) : "f"(v.x));
            asm("cvt.rna.tf32.f32 %0, %1;" : "=r"(t1) : "f"(v.y));
            asm("cvt.rna.tf32.f32 %0, %1;" : "=r"(t2) : "f"(v.z));
            asm("cvt.rna.tf32.f32 %0, %1;" : "=r"(t3) : "f"(v.w));
            *reinterpret_cast<float4*>(&As[row * LDK + col]) =
                make_float4(__uint_as_float(t0), __uint_as_float(t1),
                            __uint_as_float(t2), __uint_as_float(t3));
        }
        for (int i = tid; i < 64 * 39; i += 256) {
            int row = i / 39, q = i % 39;
            int col = q * 4;
            int gk = kbase + col;
            float4 x = make_float4(0.f, 0.f, 0.f, 0.f);
            if (q < 38)
                x = *reinterpret_cast<const float4*>(&g_WheadT[(size_t)(n0 + row) * KHP + gk]);
            unsigned t0, t1, t2, t3;
            asm("cvt.rna.tf32.f32 %0, %1;" : "=r"(t0) : "f"(x.x));
            asm("cvt.rna.tf32.f32 %0, %1;" : "=r"(t1) : "f"(x.y));
            asm("cvt.rna.tf32.f32 %0, %1;" : "=r"(t2) : "f"(x.z));
            asm("cvt.rna.tf32.f32 %0, %1;" : "=r"(t3) : "f"(x.w));
            *reinterpret_cast<float4*>(&Bs[row * LDK + col]) =
                make_float4(__uint_as_float(t0), __uint_as_float(t1),
                            __uint_as_float(t2), __uint_as_float(t3));
        }
        __syncthreads();

        const float* Ap = As + (wm * 16 + gid) * LDK + tig;
#pragma unroll
        for (int ks = 0; ks < 19; ks++) {
            int k = ks * 8;
            unsigned a0 = __float_as_uint(Ap[k]);
            unsigned a1 = __float_as_uint(Ap[8 * LDK + k]);
            unsigned a2 = __float_as_uint(Ap[k + 4]);
            unsigned a3 = __float_as_uint(Ap[8 * LDK + k + 4]);
#pragma unroll
            for (int nt = 0; nt < 4; nt++) {
                const float* Bp = Bs + (wn * 32 + nt * 8 + gid) * LDK + tig + k;
                unsigned b0 = __float_as_uint(Bp[0]);
                unsigned b1v = __float_as_uint(Bp[4]);
                asm volatile(
                    "mma.sync.aligned.m16n8k8.row.col.f32.tf32.tf32.f32 "
                    "{%0,%1,%2,%3}, {%4,%5,%6,%7}, {%8,%9}, {%0,%1,%2,%3};"
                    : "+f"(c[nt][0]), "+f"(c[nt][1]), "+f"(c[nt][2]), "+f"(c[nt][3])
                    : "r"(a0), "r"(a1), "r"(a2), "r"(a3), "r"(b0), "r"(b1v));
            }
        }
    }

    int r0 = m0 + wm * 16 + gid;
    int colbase = n0 + wn * 32 + tig * 2;
#pragma unroll
    for (int nt = 0; nt < 4; nt++) {
#pragma unroll
        for (int j = 0; j < 2; j++) {
            int col = colbase + nt * 8 + j;
            float v0 = c[nt][j], v1 = c[nt][2 + j];
            if (col < 50) {
                float bb = __ldg(&bmu[col]);
                g_mu[(size_t)r0 * Tn + col] = v0 + bb;
                g_mu[(size_t)(r0 + 8) * Tn + col] = v1 + bb;
            } else if (col < 100) {
                float bb = __ldg(&blv[col - 50]);
                g_lv[(size_t)r0 * Tn + (col - 50)] = v0 + bb;
                g_lv[(size_t)(r0 + 8) * Tn + (col - 50)] = v1 + bb;
            }
        }
    }
}

// ---------------- logitsT[v][64] via tf32 mma + fused transpose + max partials -------
__global__ void k_logits_mma(const float* __restrict__ alpha, const float* __restrict__ rho)
{
    extern __shared__ float sm[];
    float* As = sm;
    float* Bs = sm + 64 * LDK;
    __shared__ float pmax[2][64];
    int tid = threadIdx.x;
    int lane = tid & 31, warp = tid >> 5;
    int gid = lane >> 2, tig = lane & 3;
    int wm = warp >> 1, wn = warp & 1;
    int v0 = blockIdx.x * 64;
    float c[4][4] = {};

    for (int ch = 0; ch < 2; ch++) {
        int kbase = ch * KCH;
        __syncthreads();
        for (int i = tid; i < 64 * 39; i += 256) {
            int row = i / 39, q = i % 39;
            int col = q * 4;
            int gk = kbase + col;
            float4 v = make_float4(0.f, 0.f, 0.f, 0.f);
            if (q < 38 && row < Tn && gk < En)
                v = *reinterpret_cast<const float4*>(&alpha[(size_t)row * En + gk]);
            unsigned t0, t1, t2, t3;
            asm("cvt.rna.tf32.f32 %0, %1;" : "=r"(t0) : "f"(v.x));
            asm("cvt.rna.tf32.f32 %0, %1;" : "=r"(t1) : "f"(v.y));
            asm("cvt.rna.tf32.f32 %0, %1;" : "=r"(t2) : "f"(v.z));
            asm("cvt.rna.tf32.f32 %0, %1;" : "=r"(t3) : "f"(v.w));
            *reinterpret_cast<float4*>(&As[row * LDK + col]) =
                make_float4(__uint_as_float(t0), __uint_as_float(t1),
                            __uint_as_float(t2), __uint_as_float(t3));
        }
        for (int i = tid; i < 64 * 39; i += 256) {
            int row = i / 39, q = i % 39;
            int col = q * 4;
            int gk = kbase + col;
            int v = v0 + row;
            float4 x = make_float4(0.f, 0.f, 0.f, 0.f);
            if (q < 38 && v < Vn && gk < En)
                x = *reinterpret_cast<const float4*>(&rho[(size_t)v * En + gk]);
            unsigned t0, t1, t2, t3;
            asm("cvt.rna.tf32.f32 %0, %1;" : "=r"(t0) : "f"(x.x));
            asm("cvt.rna.tf32.f32 %0, %1;" : "=r"(t1) : "f"(x.y));
            asm("cvt.rna.tf32.f32 %0, %1;" : "=r"(t2) : "f"(x.z));
            asm("cvt.rna.tf32.f32 %0, %1;" : "=r"(t3) : "f"(x.w));
            *reinterpret_cast<float4*>(&Bs[row * LDK + col]) =
                make_float4(__uint_as_float(t0), __uint_as_float(t1),
                            __uint_as_float(t2), __uint_as_float(t3));
        }
        __syncthreads();

        const float* Ap = As + (wm * 16 + gid) * LDK + tig;
#pragma unroll
        for (int ks = 0; ks < 19; ks++) {
            int k = ks * 8;
            unsigned a0 = __float_as_uint(Ap[k]);
            unsigned a1 = __float_as_uint(Ap[8 * LDK + k]);
            unsigned a2 = __float_as_uint(Ap[k + 4]);
            unsigned a3 = __float_as_uint(Ap[8 * LDK + k + 4]);
#pragma unroll
            for (int nt = 0; nt < 4; nt++) {
                const float* Bp = Bs + (wn * 32 + nt * 8 + gid) * LDK + tig + k;
                unsigned b0 = __float_as_uint(Bp[0]);
                unsigned b1 = __float_as_uint(Bp[4]);
                asm volatile(
                    "mma.sync.aligned.m16n8k8.row.col.f32.tf32.tf32.f32 "
                    "{%0,%1,%2,%3}, {%4,%5,%6,%7}, {%8,%9}, {%0,%1,%2,%3};"
                    : "+f"(c[nt][0]), "+f"(c[nt][1]), "+f"(c[nt][2]), "+f"(c[nt][3])
                    : "r"(a0), "r"(a1), "r"(a2), "r"(a3), "r"(b0), "r"(b1));
            }
        }
    }

    int colbase = v0 + wn * 32 + tig * 2;
    float m0 = -1e30f, m1 = -1e30f;
#pragma unroll
    for (int nt = 0; nt < 4; nt++) {
        int cA = colbase + nt * 8;
        if (cA < Vn)     { m0 = fmaxf(m0, c[nt][0]); m1 = fmaxf(m1, c[nt][2]); }
        if (cA + 1 < Vn) { m0 = fmaxf(m0, c[nt][1]); m1 = fmaxf(m1, c[nt][3]); }
    }
    m0 = fmaxf(m0, __shfl_xor_sync(0xffffffffu, m0, 1));
    m0 = fmaxf(m0, __shfl_xor_sync(0xffffffffu, m0, 2));
    m1 = fmaxf(m1, __shfl_xor_sync(0xffffffffu, m1, 1));
    m1 = fmaxf(m1, __shfl_xor_sync(0xffffffffu, m1, 2));
    if (tig == 0) {
        pmax[wn][wm * 16 + gid]     = m0;
        pmax[wn][wm * 16 + gid + 8] = m1;
    }
    __syncthreads();
    if (tid < 64)
        g_bmax[blockIdx.x * 64 + tid] = fmaxf(pmax[0][tid], pmax[1][tid]);

    float* sT = sm;  // [64][65]
#pragma unroll
    for (int nt = 0; nt < 4; nt++) {
        int vl = wn * 32 + nt * 8 + tig * 2;
        int r = wm * 16 + gid;
        sT[vl * 65 + r]           = c[nt][0];
        sT[(vl + 1) * 65 + r]     = c[nt][1];
        sT[vl * 65 + r + 8]       = c[nt][2];
        sT[(vl + 1) * 65 + r + 8] = c[nt][3];
    }
    __syncthreads();
#pragma unroll
    for (int rep = 0; rep < 16; rep++) {
        int idx = rep * 256 + tid;
        int vl = idx >> 6, t = idx & 63;
        int v = v0 + vl;
        if (v < Vn) g_betaT[(size_t)v * 64 + t] = sT[vl * 65 + t];
    }
}

// ---------------- combine max partials (grid 64) ----------------
__global__ void k_maxcomb()
{
    __shared__ float red[256];
    int t = blockIdx.x, tid = threadIdx.x;
    float m = -1e30f;
#pragma unroll 4
    for (int i = tid; i < NBLK; i += 256) m = fmaxf(m, g_bmax[i * 64 + t]);
    red[tid] = m; __syncthreads();
    for (int o = 128; o; o >>= 1) {
        if (tid < o) red[tid] = fmaxf(red[tid], red[tid + o]);
        __syncthreads();
    }
    if (tid == 0) g_rmax[t] = red[0];
}

// ---------------- exp in place + sum partials ----------------
__global__ void k_beta_exp()
{
    __shared__ float srmax[64];
    __shared__ float ssum[16][64];
    int tid = threadIdx.x;
    if (tid < 64) srmax[tid] = g_rmax[tid];
    __syncthreads();
    float4* P = reinterpret_cast<float4*>(g_betaT);
    size_t base = (size_t)blockIdx.x * 4096;
    int t0 = (tid & 15) * 4;
    float rm0 = srmax[t0], rm1 = srmax[t0 + 1], rm2 = srmax[t0 + 2], rm3 = srmax[t0 + 3];
    float s0 = 0.f, s1 = 0.f, s2 = 0.f, s3 = 0.f;
#pragma unroll
    for (int k = 0; k < 16; k++) {
        size_t idx = base + (size_t)k * 256 + tid;
        if (idx < (size_t)Vn * 16) {
            float4 x = P[idx];
            x.x = expf(x.x - rm0);
            x.y = expf(x.y - rm1);
            x.z = expf(x.z - rm2);
            x.w = expf(x.w - rm3);
            s0 += x.x; s1 += x.y; s2 += x.z; s3 += x.w;
            P[idx] = x;
        }
    }
    int g = tid >> 4;
    ssum[g][t0 + 0] = s0; ssum[g][t0 + 1] = s1;
    ssum[g][t0 + 2] = s2; ssum[g][t0 + 3] = s3;
    __syncthreads();
    if (tid < 64) {
        float s = 0.f;
#pragma unroll
        for (int i = 0; i < 16; i++) s += ssum[i][tid];
        g_bsum[blockIdx.x * 64 + tid] = s;
    }
}

// ---------------- combine sum partials -> rinv (grid 64) ----------------
__global__ void k_sumcomb()
{
    __shared__ float red[256];
    int t = blockIdx.x, tid = threadIdx.x;
    float s = 0.f;
    if (tid < NEXP) s = g_bsum[tid * 64 + t];
    red[tid] = s; __syncthreads();
    for (int o = 128; o; o >>= 1) {
        if (tid < o) red[tid] += red[tid + o];
        __syncthreads();
    }
    if (tid == 0) g_rinv[t] = 1.0f / red[0];
}

// ---------------- kl + theta softmax; runs in chain A (no rinv dependency) ----------
__global__ void k_theta_kl(float* __restrict__ out)
{
    int b = blockIdx.x, t = threadIdx.x;
    __shared__ float red[64];
    bool ok = (t < Tn);
    float mu = 0.f, lv = 0.f;
    if (ok) { mu = g_mu[b * Tn + t]; lv = g_lv[b * Tn + t]; }
    float kle = ok ? (1.f + lv - mu * mu - expf(lv)) : 0.f;
    red[t] = kle; __syncthreads();
    for (int o = 32; o; o >>= 1) { if (t < o) red[t] += red[t + o]; __syncthreads(); }
    if (t == 0) g_kl[b] = -0.5f * red[0];
    __syncthreads();
    red[t] = ok ? mu : -1e30f; __syncthreads();
    for (int o = 32; o; o >>= 1) { if (t < o) red[t] = fmaxf(red[t], red[t + o]); __syncthreads(); }
    float mx = red[0]; __syncthreads();
    float e = ok ? expf(mu - mx) : 0.f;
    red[t] = e; __syncthreads();
    for (int o = 32; o; o >>= 1) { if (t < o) red[t] += red[t + o]; __syncthreads(); }
    float inv = 1.0f / red[0];
    float th = e * inv;
    if (ok) out[b * Tn + t] = th;
    g_theta[b * 64 + t] = ok ? th : 0.f;   // unscaled (rinv applied in recon)
}

// ---------------- recon: applies rinv to theta at load; 13 float4/token ----------
__global__ void k_recon(const int* __restrict__ ids)
{
    __shared__ float th[64];
    __shared__ float red[256];
    int b = blockIdx.x, tid = threadIdx.x;
    if (tid < 64) th[tid] = g_theta[b * 64 + tid] * g_rinv[tid];
    __syncthreads();
    float acc = 0.f;
#pragma unroll 1
    for (int s = tid; s < Sn; s += 256) {
        int v = ids[b * Sn + s];
        if (v == 1 || v == 2) continue;
        const float4* p = reinterpret_cast<const float4*>(g_betaT + (size_t)v * 64);
        float d = 0.f;
#pragma unroll
        for (int i = 0; i < 13; i++) {
            float4 bv = p[i];
            float4 tv = *reinterpret_cast<const float4*>(&th[i * 4]);
            d += bv.x*tv.x + bv.y*tv.y + bv.z*tv.z + bv.w*tv.w;
        }
        acc += logf(d + 1e-5f);
    }
    red[tid] = acc; __syncthreads();
    for (int o = 128; o; o >>= 1) { if (tid < o) red[tid] += red[tid + o]; __syncthreads(); }
    if (tid == 0) g_recon[b] = -red[0];
}

// ---------------- final loss ----------------
__global__ void k_loss(float* __restrict__ out, int loss_idx)
{
    __shared__ float r1[1024];
    __shared__ float r2[1024];
    int t = threadIdx.x;
    r1[t] = g_recon[t]; r2[t] = g_kl[t];
    __syncthreads();
    for (int o = 512; o; o >>= 1) {
        if (t < o) { r1[t] += r1[t + o]; r2[t] += r2[t + o]; }
        __syncthreads();
    }
    if (t == 0) out[loss_idx] = (r1[0] + r2[0]) * (1.0f / (float)Bn);
}

// ---------------- launch ----------------
extern "C" void kernel_launch(void* const* d_in, const int* in_sizes, int n_in,
                              void* d_out, int out_size)
{
    const int*   ids   = (const int*)d_in[0];
    const float* rho   = (const float*)d_in[1];
    const float* alpha = (const float*)d_in[2];
    const float* W1    = (const float*)d_in[3];
    const float* b1    = (const float*)d_in[4];
    const float* Wmu   = (const float*)d_in[5];
    const float* bmu   = (const float*)d_in[6];
    const float* Wlv   = (const float*)d_in[7];
    const float* blv   = (const float*)d_in[8];
    float* out = (float*)d_out;

    static cudaStream_t s2 = nullptr;
    static cudaEvent_t ev_fork = nullptr, ev_join = nullptr, ev_w = nullptr;
    static bool smem_set = false;
    if (!s2) {
        cudaStreamCreateWithFlags(&s2, cudaStreamNonBlocking);
        cudaEventCreateWithFlags(&ev_fork, cudaEventDisableTiming);
        cudaEventCreateWithFlags(&ev_join, cudaEventDisableTiming);
        cudaEventCreateWithFlags(&ev_w, cudaEventDisableTiming);
    }
    if (!smem_set) {
        int smem0 = 2 * 64 * LDK * (int)sizeof(float);
        cudaFuncSetAttribute(k_logits_mma, cudaFuncAttributeMaxDynamicSharedMemorySize, smem0);
        cudaFuncSetAttribute(k_hgemm_mma, cudaFuncAttributeMaxDynamicSharedMemorySize, smem0);
        cudaFuncSetAttribute(k_head_mma, cudaFuncAttributeMaxDynamicSharedMemorySize, smem0);
        smem_set = true;
    }
    int smem = 2 * 64 * LDK * sizeof(float);  // 79872 B

    // fork: chain B on s2
    cudaEventRecord(ev_fork, 0);
    cudaStreamWaitEvent(s2, ev_fork, 0);

    // chain B: weight transposes (feed chain A), then logits/softmax stats
    k_transW1<<<dim3(25, 10), 256, 0, s2>>>(W1);
    k_transWhead<<<(128 * KHP + 255) / 256, 256, 0, s2>>>(Wmu, Wlv);
    cudaEventRecord(ev_w, s2);
    k_logits_mma<<<NBLK, 256, smem, s2>>>(alpha, rho);
    k_maxcomb<<<64, 256, 0, s2>>>();
    k_beta_exp<<<NEXP, 256, 0, s2>>>();
    k_sumcomb<<<64, 256, 0, s2>>>();
    cudaEventRecord(ev_join, s2);

    // chain A: gather -> h-gemm -> head -> theta/kl (all independent of chain B)
    k_gather<<<Bn, 320>>>(ids, rho);
    cudaStreamWaitEvent(0, ev_w, 0);
    k_hgemm_mma<<<dim3(13, 16), 256, smem>>>(b1);
    k_head_mma<<<dim3(2, 16), 256, smem>>>(bmu, blv);
    k_theta_kl<<<Bn, 64>>>(out);     // overlaps chain B's beta_exp

    // join: recon needs betaT+rinv (B) and theta (A)
    cudaStreamWaitEvent(0, ev_join, 0);
    k_recon<<<Bn, 256>>>(ids);
    k_loss<<<1, 1024>>>(out, out_size - 1);
}